// round 6
// baseline (speedup 1.0000x reference)
#include <cuda_runtime.h>
#include <cstdint>
#include <cstddef>

#define B_    2
#define C_    256
#define H_    512
#define W_    512
#define PS    52
#define NH    9
#define NW    9
#define P_    81
#define COV   468          // NH*PS
#define QQ    2704         // PS*PS
#define PLANE (H_*W_)      // 262144

// Scratch (device globals: no allocations allowed)
__device__ float d_gsum[B_*C_];
__device__ float d_S[B_*P_*256];
__device__ float d_Q[B_*P_];
__device__ int   d_sel[B_*P_];

__device__ __forceinline__ float warpReduce(float v) {
  #pragma unroll
  for (int o = 16; o > 0; o >>= 1) v += __shfl_down_sync(0xffffffffu, v, o);
  return v;
}

// ---------------------------------------------------------------- zero stats
__global__ void k_zero() {
  int i = blockIdx.x * blockDim.x + threadIdx.x;
  if (i < B_*P_*256) d_S[i] = 0.f;
  if (i < B_*C_)     d_gsum[i] = 0.f;
  if (i < B_*P_)     d_Q[i] = 0.f;
}

// ------------------------------------------- per-patch stats (covered region)
// Block = (b, pp, channel-group of 16). Thread t owns weight bin widx == t:
// for channel c it reads q = ((t - 144*c) & 255) + 256*j  (coalesced), since
// widx = (144*c + q) mod 256 == t. Accumulates S (register), Q (sumsq), and
// per-channel sums for the GAP (warp reduce + atomic).
#define CG 16
__global__ __launch_bounds__(256) void k_stats(const float* __restrict__ x) {
  int bid = blockIdx.x;
  int cg = bid & 15;                 // C_/CG == 16 groups
  int pp = (bid >> 4) % P_;
  int b  = bid / (16 * P_);
  int ph = pp / NW, pw = pp - ph * NW;
  int t = threadIdx.x;
  int lane = t & 31, warp = t >> 5;

  const float* pbase = x + (size_t)b * C_ * PLANE + (size_t)(ph * PS) * W_ + pw * PS;

  float acc = 0.f;    // S bin t
  float qacc = 0.f;   // sum of squares
  for (int cc = 0; cc < CG; ++cc) {
    int c = cg * CG + cc;
    const float* cb = pbase + (size_t)c * PLANE;
    int q0 = (t - 144 * c) & 255;
    float csum = 0.f;
    for (int q = q0; q < QQ; q += 256) {
      int kh = q / PS;
      int kw = q - kh * PS;
      float v = __ldg(cb + kh * W_ + kw);
      acc += v;
      csum += v;
      qacc = fmaf(v, v, qacc);
    }
    csum = warpReduce(csum);
    if (lane == 0) atomicAdd(&d_gsum[b * C_ + c], csum);
  }
  atomicAdd(&d_S[(b * P_ + pp) * 256 + t], acc);

  __shared__ float qred[8];
  qacc = warpReduce(qacc);
  if (lane == 0) qred[warp] = qacc;
  __syncthreads();
  if (warp == 0) {
    float v = (lane < 8) ? qred[lane] : 0.f;
    v = warpReduce(v);
    if (lane == 0) atomicAdd(&d_Q[b * P_ + pp], v);
  }
}

// -------------------------------------------------- GAP over uncovered border
// border per plane: rows 0..467 cols 468..511 (468*44=20592) + rows 468..511
// all cols (44*512=22528) = 43120 elements.
__global__ __launch_bounds__(256) void k_border_g(const float* __restrict__ x) {
  int plane = blockIdx.y;                    // 0..B_*C_-1
  const float* pb = x + (size_t)plane * PLANE;
  float s = 0.f;
  for (int j = blockIdx.x * blockDim.x + threadIdx.x; j < 43120;
       j += gridDim.x * blockDim.x) {
    int r, col;
    if (j < 20592) { r = j / 44; col = 468 + (j - r * 44); }
    else           { int j2 = j - 20592; r = 468 + (j2 >> 9); col = j2 & 511; }
    s += pb[(size_t)r * W_ + col];
  }
  __shared__ float red[8];
  int lane = threadIdx.x & 31, warp = threadIdx.x >> 5;
  s = warpReduce(s);
  if (lane == 0) red[warp] = s;
  __syncthreads();
  if (warp == 0) {
    float v = (lane < 8) ? red[lane] : 0.f;
    v = warpReduce(v);
    if (lane == 0) atomicAdd(&d_gsum[plane], v);
  }
}

// ----------------------------------------------- cosine, argmax/argmin, sel[]
__global__ __launch_bounds__(256) void k_select() {
  int b = blockIdx.x;
  int t = threadIdx.x;
  int lane = t & 31, warp = t >> 5;
  __shared__ float g_s[256];
  __shared__ float red[8];
  __shared__ float cos_s[P_];
  __shared__ int mm[2];

  float gv = d_gsum[b * C_ + t] * (1.0f / (float)PLANE);
  g_s[t] = gv;
  float gg = warpReduce(gv * gv);
  if (lane == 0) red[warp] = gg;
  __syncthreads();
  if (warp == 0) {
    float v = (lane < 8) ? red[lane] : 0.f;
    v = warpReduce(v);
    if (lane == 0) red[0] = v;
  }
  __syncthreads();
  float gnorm = sqrtf(red[0]) * (float)PS;

  for (int pp = warp; pp < P_; pp += 8) {
    const float* Sp = d_S + (b * P_ + pp) * 256;
    float d = 0.f;
    #pragma unroll
    for (int l = 0; l < 8; ++l) d += Sp[lane + 32 * l] * g_s[lane + 32 * l];
    d = warpReduce(d);
    if (lane == 0) {
      float pn = sqrtf(d_Q[b * P_ + pp]);
      cos_s[pp] = d / fmaxf(gnorm * pn, 1e-8f);
    }
  }
  __syncthreads();
  if (t == 0) {
    float vmax = cos_s[0], vmin = cos_s[0];
    int imax = 0, imin = 0;
    for (int i = 1; i < P_; ++i) {   // strict compare -> first occurrence (jnp)
      float cv = cos_s[i];
      if (cv > vmax) { vmax = cv; imax = i; }
      if (cv < vmin) { vmin = cv; imin = i; }
    }
    mm[0] = imax; mm[1] = imin;
  }
  __syncthreads();
  if (t < P_) d_sel[b * P_ + t] = (t == mm[0]) ? mm[1] : t;
}

// ------------------------------------------------------- apply mask (covered)
// Block = (b, pp, kh, half). Handles 26 output columns x 256 channels.
// m = (kh*52 + kw)*256 + c_out; consecutive m => consecutive SOURCE addresses
// (float4, never straddles a source row or channel since 52 and 2704 are
// multiples of 4). Stage in smem with stride-257 padding, then emit coalesced
// float2 writes per (c_out, kw).
__global__ __launch_bounds__(512) void k_apply(const float* __restrict__ x,
                                               float* __restrict__ out) {
  __shared__ float sbuf[26 * 257];   // 26.7 KB
  int lin = blockIdx.x;
  int half = lin & 1;
  int kh = (lin >> 1) % PS;
  int pp = ((lin >> 1) / PS) % P_;
  int b  = lin / (2 * PS * P_);
  int ph = pp / NW, pw = pp - ph * NW;
  int sp = d_sel[b * P_ + pp];
  int sph = sp / NW, spw = sp - sph * NW;
  int t = threadIdx.x;

  const float* xb = x + (size_t)b * C_ * PLANE;
  const float* src = xb + (size_t)(sph * PS) * W_ + spw * PS;
  int m0 = (kh * PS + half * 26) << 8;

  // gather 6656 source elements (1664 float4), source-linear (coalesced)
  for (int i4 = t; i4 < 1664; i4 += 512) {
    int i = i4 << 2;
    int m = m0 + i;
    int cs  = m / QQ;
    int r   = m - cs * QQ;
    int khs = r / PS;
    int kws = r - khs * PS;
    float4 v = *reinterpret_cast<const float4*>(src + (size_t)cs * PLANE +
                                                khs * W_ + kws);
    int si = i + (i >> 8);           // layout: kw_local*257 + c_out
    sbuf[si]     = v.x;
    sbuf[si + 1] = v.y;
    sbuf[si + 2] = v.z;
    sbuf[si + 3] = v.w;
  }
  __syncthreads();

  int h  = ph * PS + kh;
  int wb = pw * PS + half * 26;
  // write side: (c_out, kw) order, float2 coalesced
  for (int i2 = t; i2 < 3328; i2 += 512) {
    int co  = i2 / 13;
    int kwl = (i2 - co * 13) << 1;
    float ma = sbuf[kwl * 257 + co];
    float mb = sbuf[(kwl + 1) * 257 + co];
    size_t off = ((size_t)(b * C_ + co) * H_ + h) * W_ + wb + kwl;
    float2 xv = *reinterpret_cast<const float2*>(x + off);
    float2 ov;
    ov.x = ma * xv.x;
    ov.y = mb * xv.y;
    *reinterpret_cast<float2*>(out + off) = ov;
  }
}

// ------------------------------------------------------------ zero the border
// R1: 468 rows x 44 cols (11 quads), R2: 44 rows x 512 cols (128 quads)
__global__ __launch_bounds__(256) void k_border_out(float* __restrict__ out) {
  int plane = blockIdx.y;
  size_t pb = (size_t)plane * PLANE;
  float4 z = make_float4(0.f, 0.f, 0.f, 0.f);
  for (int i = blockIdx.x * blockDim.x + threadIdx.x; i < 10780;
       i += gridDim.x * blockDim.x) {
    size_t off;
    if (i < 5148) { int r = i / 11; int cq = i - r * 11;
                    off = pb + (size_t)r * W_ + 468 + (cq << 2); }
    else          { int j = i - 5148; int r = j >> 7; int cq = j & 127;
                    off = pb + (size_t)(468 + r) * W_ + (cq << 2); }
    *reinterpret_cast<float4*>(out + off) = z;
  }
}

extern "C" void kernel_launch(void* const* d_in, const int* in_sizes, int n_in,
                              void* d_out, int out_size) {
  (void)in_sizes; (void)n_in; (void)out_size;
  const float* x = (const float*)d_in[0];
  float* out = (float*)d_out;

  k_zero<<<162, 256>>>();
  k_stats<<<B_ * P_ * 16, 256>>>(x);
  k_border_g<<<dim3(22, B_ * C_), 256>>>(x);
  k_select<<<B_, 256>>>();
  k_border_out<<<dim3(11, B_ * C_), 256>>>(out);
  k_apply<<<B_ * P_ * PS * 2, 512>>>(x, out);
}

// round 7
// speedup vs baseline: 1.2015x; 1.2015x over previous
#include <cuda_runtime.h>
#include <cstdint>
#include <cstddef>

#define B_    2
#define C_    256
#define H_    512
#define W_    512
#define PS    52
#define NH    9
#define NW    9
#define P_    81
#define QQ    2704         // PS*PS
#define PLANE (H_*W_)      // 262144

// Scratch (device globals: no allocations allowed)
__device__ float d_gsum[B_*C_];
__device__ float d_S16[B_*P_*16*256];   // per (b,pp,cg) partial weighted sums
__device__ float d_Q16[B_*P_*16];       // per (b,pp,cg) partial sumsq
__device__ float d_cos[B_*P_];
__device__ int   d_sel[B_*P_];

__device__ __forceinline__ float warpReduce(float v) {
  #pragma unroll
  for (int o = 16; o > 0; o >>= 1) v += __shfl_down_sync(0xffffffffu, v, o);
  return v;
}

// ---------------------------------------------------- zero gsum (512 floats)
__global__ void k_zero() {
  int i = threadIdx.x;
  if (i < B_*C_) d_gsum[i] = 0.f;
}

// ------------------------------------------- per-patch stats (covered region)
// Block = (b, pp, channel-group of 16). Thread t owns weight bin widx == t:
// for channel c it reads q = ((t - 144*c) & 255) + 256*j (coalesced), since
// widx = (144*c + q) mod 256 == t. Fixed 11-trip predicated loop -> full
// unroll, 11 LDGs in flight. S/Q written as per-block partials (no atomics).
#define CG 16
__global__ __launch_bounds__(256) void k_stats(const float* __restrict__ x) {
  int bid = blockIdx.x;
  int cg = bid & 15;                 // C_/CG == 16 groups
  int pp = (bid >> 4) % P_;
  int b  = bid / (16 * P_);
  int ph = pp / NW, pw = pp - ph * NW;
  int t = threadIdx.x;
  int lane = t & 31, warp = t >> 5;

  const float* pbase = x + (size_t)b * C_ * PLANE + (size_t)(ph * PS) * W_ + pw * PS;

  float acc = 0.f;    // S bin t
  float qacc = 0.f;   // sum of squares
  #pragma unroll 1
  for (int cc = 0; cc < CG; ++cc) {
    int c = cg * CG + cc;
    const float* cb = pbase + (size_t)c * PLANE;
    int q0 = (t - 144 * c) & 255;
    float csum = 0.f;
    #pragma unroll
    for (int j = 0; j < 11; ++j) {
      int q = q0 + 256 * j;
      int kh = q / PS;
      int kw = q - kh * PS;
      float v = (q < QQ) ? __ldg(cb + kh * W_ + kw) : 0.f;
      acc += v;
      csum += v;
      qacc = fmaf(v, v, qacc);
    }
    csum = warpReduce(csum);
    if (lane == 0) atomicAdd(&d_gsum[b * C_ + c], csum);
  }
  d_S16[((size_t)(b * P_ + pp) * 16 + cg) * 256 + t] = acc;

  __shared__ float qred[8];
  qacc = warpReduce(qacc);
  if (lane == 0) qred[warp] = qacc;
  __syncthreads();
  if (warp == 0) {
    float v = (lane < 8) ? qred[lane] : 0.f;
    v = warpReduce(v);
    if (lane == 0) d_Q16[(b * P_ + pp) * 16 + cg] = v;
  }
}

// -------------------------------------------------- GAP over uncovered border
// border per plane: rows 0..467 cols 468..511 (468*44=20592) + rows 468..511
// all cols (44*512=22528) = 43120 elements.
__global__ __launch_bounds__(256) void k_border_g(const float* __restrict__ x) {
  int plane = blockIdx.y;                    // 0..B_*C_-1
  const float* pb = x + (size_t)plane * PLANE;
  float s = 0.f;
  for (int j = blockIdx.x * blockDim.x + threadIdx.x; j < 43120;
       j += gridDim.x * blockDim.x) {
    int r, col;
    if (j < 20592) { r = j / 44; col = 468 + (j - r * 44); }
    else           { int j2 = j - 20592; r = 468 + (j2 >> 9); col = j2 & 511; }
    s += pb[(size_t)r * W_ + col];
  }
  __shared__ float red[8];
  int lane = threadIdx.x & 31, warp = threadIdx.x >> 5;
  s = warpReduce(s);
  if (lane == 0) red[warp] = s;
  __syncthreads();
  if (warp == 0) {
    float v = (lane < 8) ? red[lane] : 0.f;
    v = warpReduce(v);
    if (lane == 0) atomicAdd(&d_gsum[plane], v);
  }
}

// --------------------------------------------- cosine per patch (grid 2*81)
__global__ __launch_bounds__(256) void k_cos() {
  int bp = blockIdx.x;               // b*81 + pp
  int b = bp / P_;
  int t = threadIdx.x;
  int lane = t & 31, warp = t >> 5;

  float g = d_gsum[b * C_ + t] * (1.0f / (float)PLANE);
  float s = 0.f;
  const float* Sp = d_S16 + (size_t)bp * 16 * 256 + t;
  #pragma unroll
  for (int cg = 0; cg < 16; ++cg) s += Sp[cg * 256];

  float dotv = s * g;
  float gg = g * g;
  __shared__ float rd[8], rg[8];
  dotv = warpReduce(dotv);
  gg = warpReduce(gg);
  if (lane == 0) { rd[warp] = dotv; rg[warp] = gg; }
  __syncthreads();
  if (t == 0) {
    float D = 0.f, G = 0.f;
    #pragma unroll
    for (int i = 0; i < 8; ++i) { D += rd[i]; G += rg[i]; }
    float q = 0.f;
    const float* Qp = d_Q16 + bp * 16;
    #pragma unroll
    for (int i = 0; i < 16; ++i) q += Qp[i];
    float gnorm = sqrtf(G) * (float)PS;
    float pnorm = sqrtf(q);
    d_cos[bp] = D / fmaxf(gnorm * pnorm, 1e-8f);
  }
}

// --------------------------------------------------- argmax/argmin -> sel[]
__global__ __launch_bounds__(128) void k_sel() {
  int b = blockIdx.x;
  int t = threadIdx.x;
  __shared__ float cs[P_];
  __shared__ int mm[2];
  if (t < P_) cs[t] = d_cos[b * P_ + t];
  __syncthreads();
  if (t == 0) {
    float vmax = cs[0], vmin = cs[0];
    int imax = 0, imin = 0;
    for (int i = 1; i < P_; ++i) {   // strict compare -> first occurrence (jnp)
      float cv = cs[i];
      if (cv > vmax) { vmax = cv; imax = i; }
      if (cv < vmin) { vmin = cv; imin = i; }
    }
    mm[0] = imax; mm[1] = imin;
  }
  __syncthreads();
  if (t < P_) d_sel[b * P_ + t] = (t == mm[0]) ? mm[1] : t;
}

// ------------------------------------------------------- apply mask (covered)
// Block = (b, pp, kh, channel-half of 128). Covers all 52 output columns of
// row h = ph*52+kh for 128 channels. m = (kh*52 + kw)*256 + c_out; consecutive
// m => consecutive SOURCE addresses (float4 never straddles a source row or
// channel: 52 and 2704 are multiples of 4). Stage in smem [kw][cl] with odd
// stride 137 (STS conflict-free, LDS <=2-way), then float4 coalesced
// read-modify-write of 208B channel-row segments.
__global__ __launch_bounds__(512) void k_apply(const float* __restrict__ x,
                                               float* __restrict__ out) {
  __shared__ float sbuf[PS * 137];   // 28.5 KB
  int lin = blockIdx.x;
  int chalf = lin & 1;
  int kh = (lin >> 1) % PS;
  int pp = ((lin >> 1) / PS) % P_;
  int b  = lin / (2 * PS * P_);
  int ph = pp / NW, pw = pp - ph * NW;
  int sp = d_sel[b * P_ + pp];
  int sph = sp / NW, spw = sp - sph * NW;
  int t = threadIdx.x;
  int c0 = chalf * 128;

  const float* xb = x + (size_t)b * C_ * PLANE;
  const float* src = xb + (size_t)(sph * PS) * W_ + spw * PS;
  int mbase = kh * PS * 256 + c0;

  // gather 6656 source elements (1664 float4), source-linear (coalesced)
  for (int i4 = t; i4 < 1664; i4 += 512) {
    int i = i4 << 2;
    int kw = i >> 7;                 // element (kw, cl), cl in [0,128)
    int cl = i & 127;
    int m = mbase + kw * 256 + cl;
    int cs  = m / QQ;
    int r   = m - cs * QQ;
    int khs = r / PS;
    int kws = r - khs * PS;
    float4 v = *reinterpret_cast<const float4*>(src + (size_t)cs * PLANE +
                                                khs * W_ + kws);
    int si = kw * 137 + cl;
    sbuf[si]     = v.x;
    sbuf[si + 1] = v.y;
    sbuf[si + 2] = v.z;
    sbuf[si + 3] = v.w;
  }
  __syncthreads();

  int h  = ph * PS + kh;
  int wb = pw * PS;
  // write side: per channel 13 float4 quads covering 52 cols (coalesced)
  for (int i4 = t; i4 < 1664; i4 += 512) {
    int col_ = i4 / 13;              // channel-local
    int kwq  = i4 - col_ * 13;
    int kw0  = kwq << 2;
    float m0v = sbuf[(kw0    ) * 137 + col_];
    float m1v = sbuf[(kw0 + 1) * 137 + col_];
    float m2v = sbuf[(kw0 + 2) * 137 + col_];
    float m3v = sbuf[(kw0 + 3) * 137 + col_];
    size_t off = ((size_t)(b * C_ + c0 + col_) * H_ + h) * W_ + wb + kw0;
    float4 xv = *reinterpret_cast<const float4*>(x + off);
    float4 ov;
    ov.x = m0v * xv.x;
    ov.y = m1v * xv.y;
    ov.z = m2v * xv.z;
    ov.w = m3v * xv.w;
    *reinterpret_cast<float4*>(out + off) = ov;
  }
}

// ------------------------------------------------------------ zero the border
// R1: 468 rows x 44 cols (11 quads), R2: 44 rows x 512 cols (128 quads)
__global__ __launch_bounds__(256) void k_border_out(float* __restrict__ out) {
  int plane = blockIdx.y;
  size_t pb = (size_t)plane * PLANE;
  float4 z = make_float4(0.f, 0.f, 0.f, 0.f);
  for (int i = blockIdx.x * blockDim.x + threadIdx.x; i < 10780;
       i += gridDim.x * blockDim.x) {
    size_t off;
    if (i < 5148) { int r = i / 11; int cq = i - r * 11;
                    off = pb + (size_t)r * W_ + 468 + (cq << 2); }
    else          { int j = i - 5148; int r = j >> 7; int cq = j & 127;
                    off = pb + (size_t)(468 + r) * W_ + (cq << 2); }
    *reinterpret_cast<float4*>(out + off) = z;
  }
}

extern "C" void kernel_launch(void* const* d_in, const int* in_sizes, int n_in,
                              void* d_out, int out_size) {
  (void)in_sizes; (void)n_in; (void)out_size;
  const float* x = (const float*)d_in[0];
  float* out = (float*)d_out;

  k_zero<<<1, 512>>>();
  k_stats<<<B_ * P_ * 16, 256>>>(x);
  k_border_g<<<dim3(22, B_ * C_), 256>>>(x);
  k_cos<<<B_ * P_, 256>>>();
  k_sel<<<B_, 128>>>();
  k_border_out<<<dim3(11, B_ * C_), 256>>>(out);
  k_apply<<<B_ * P_ * PS * 2, 512>>>(x, out);
}